// round 9
// baseline (speedup 1.0000x reference)
#include <cuda_runtime.h>

#define BH 16
#define T 384
#define S 384
#define D 64
#define OUT_ELEMS (BH*T*D)   // 393216

typedef unsigned long long u64;

// Scratch projections, e-major f32: [bh][e][t] / [bh][e][s]
__device__ float4 g_qpT4[BH*D*T/4];
__device__ float4 g_kpT4[BH*D*S/4];

// ---- packed f32x2 helpers (Blackwell sm_103a) ------------------------------
__device__ __forceinline__ u64 pk2(float lo, float hi) {
    u64 r; asm("mov.b64 %0, {%1,%2};" : "=l"(r) : "f"(lo), "f"(hi)); return r;
}
__device__ __forceinline__ void upk2(u64 v, float& lo, float& hi) {
    asm("mov.b64 {%0,%1}, %2;" : "=f"(lo), "=f"(hi) : "l"(v));
}
__device__ __forceinline__ u64 add2(u64 a, u64 b) {
    u64 r; asm("add.rn.f32x2 %0, %1, %2;" : "=l"(r) : "l"(a), "l"(b)); return r;
}
__device__ __forceinline__ u64 mul2(u64 a, u64 b) {
    u64 r; asm("mul.rn.f32x2 %0, %1, %2;" : "=l"(r) : "l"(a), "l"(b)); return r;
}
__device__ __forceinline__ u64 fma2(u64 a, u64 b, u64 c) {
    u64 r; asm("fma.rn.f32x2 %0, %1, %2, %3;" : "=l"(r) : "l"(a), "l"(b), "l"(c)); return r;
}
__device__ __forceinline__ float rcpf(float x) {
    float r; asm("rcp.approx.ftz.f32 %0, %1;" : "=f"(r) : "f"(x)); return r;
}

// ---------------------------------------------------------------------------
// Phase 1: qpT[bh][e][t] = sum_d X[bh][t][d] * W[e][d]   (both q and k)
// grid (16 bh, 6 t-chunks of 64, 2 which), 256 threads
// ---------------------------------------------------------------------------
__global__ __launch_bounds__(256) void proj_kernel(
    const float* __restrict__ query, const float* __restrict__ key,
    const float* __restrict__ Wq, const float* __restrict__ Wk)
{
    __shared__ float Xs[64][65];
    __shared__ float Ws[64][65];
    int bh = blockIdx.x, chunk = blockIdx.y, which = blockIdx.z;
    const float* X = which ? key : query;
    const float* W = which ? Wk : Wq;
    float* outT = which ? (float*)g_kpT4 : (float*)g_qpT4;
    int tid = threadIdx.x;

    for (int i = tid; i < 64*64; i += 256) {
        int r = i >> 6, c = i & 63;
        Xs[r][c] = X[((size_t)bh*T + (size_t)chunk*64 + r)*D + c];
        Ws[r][c] = W[i];
    }
    __syncthreads();

    int t  = tid & 63;
    int e0 = (tid >> 6) * 16;
    float acc[16];
    #pragma unroll
    for (int k = 0; k < 16; k++) acc[k] = 0.f;

    #pragma unroll 4
    for (int d = 0; d < 64; d++) {
        float xv = Xs[t][d];
        #pragma unroll
        for (int k = 0; k < 16; k++)
            acc[k] = fmaf(xv, Ws[e0+k][d], acc[k]);
    }
    #pragma unroll
    for (int k = 0; k < 16; k++)
        outT[((size_t)bh*D + e0 + k)*T + (size_t)chunk*64 + t] = acc[k];
}

// ---------------------------------------------------------------------------
// Phase 2: fused score + softmax + attn@value.
// tanh via Pade[7/6] rational: x*(10395+1260u+21u^2)/(10395+4725u+210u^2+u^3),
// evaluated with packed f32x2 ops (fma pipe) + one scalar rcp per element
// (MUFU rt8). Moves the bottleneck off MUFU.TANH (rt16, was 65us floor).
// grid (48 t-chunks, 16 bh), 128 threads. CTA: 8 t x 384 s; thread 4t x 3 s-pairs.
// ---------------------------------------------------------------------------
__global__ __launch_bounds__(128) void attn_kernel(
    const float* __restrict__ value, const float* __restrict__ v_w,
    float* __restrict__ out, float* __restrict__ attn)
{
    __shared__ __align__(16) float sh_kp[16*384];   // 24KB chunk; aliased as scores[8][384]
    __shared__ __align__(8)  u64 sh_qp2[64][8];     // (q,q) duplicated pairs
    __shared__ __align__(8)  u64 sh_vw2[64];        // (vw,vw) pairs

    float (*scores)[384] = (float(*)[384])sh_kp;

    int bh  = blockIdx.y;
    int t0  = blockIdx.x * 8;
    int tid = threadIdx.x;

    // stage qp tile duplicated + vw duplicated
    const float* qbase = (const float*)g_qpT4 + (size_t)bh*D*T;
    for (int i = tid; i < 64*8; i += 128) {
        int e = i >> 3, tl = i & 7;
        float q = qbase[(size_t)e*T + t0 + tl];
        sh_qp2[e][tl] = pk2(q, q);
    }
    if (tid < 64) { float v = v_w[tid]; sh_vw2[tid] = pk2(v, v); }

    int sx = tid & 63;   // s-pair lane (0..63)
    int ty = tid >> 6;   // t group

    float acc[4][6];
    #pragma unroll
    for (int k = 0; k < 4; k++)
        #pragma unroll
        for (int j = 0; j < 6; j++) acc[k][j] = 0.f;

    const u64 C21    = pk2(21.f, 21.f);
    const u64 C1260  = pk2(1260.f, 1260.f);
    const u64 C10395 = pk2(10395.f, 10395.f);
    const u64 C210   = pk2(210.f, 210.f);
    const u64 C4725  = pk2(4725.f, 4725.f);

    const float4* kbase4 = g_kpT4 + (size_t)bh*D*S/4;

    for (int c = 0; c < 4; c++) {
        __syncthreads();
        // load kp chunk: 16 e-rows x 384 s f32 (24KB), coalesced float4
        const float4* src = kbase4 + (size_t)c*16*S/4;
        float4* dst = (float4*)sh_kp;
        #pragma unroll
        for (int i = tid; i < 16*384/4; i += 128) dst[i] = src[i];
        __syncthreads();

        #pragma unroll
        for (int ec = 0; ec < 16; ec++) {
            int e = c*16 + ec;
            u64 vw2 = sh_vw2[e];
            u64 q2[4], kk[3];
            #pragma unroll
            for (int k = 0; k < 4; k++) q2[k] = sh_qp2[e][ty*4 + k];
            const u64* krow = (const u64*)&sh_kp[ec*384];
            #pragma unroll
            for (int p = 0; p < 3; p++) kk[p] = krow[sx + 64*p];

            #pragma unroll
            for (int k = 0; k < 4; k++)
                #pragma unroll
                for (int p = 0; p < 3; p++) {
                    u64 x  = add2(q2[k], kk[p]);
                    u64 u  = mul2(x, x);
                    u64 pn = fma2(u, C21, C1260);
                    pn     = fma2(u, pn, C10395);
                    u64 xp = mul2(x, pn);
                    u64 qd = add2(u, C210);
                    qd     = fma2(u, qd, C4725);
                    qd     = fma2(u, qd, C10395);
                    u64 vxp = mul2(vw2, xp);
                    float ql, qh, vl, vh;
                    upk2(qd, ql, qh);
                    upk2(vxp, vl, vh);
                    acc[k][2*p]   = fmaf(vl, rcpf(ql), acc[k][2*p]);
                    acc[k][2*p+1] = fmaf(vh, rcpf(qh), acc[k][2*p+1]);
                }
        }
    }
    __syncthreads();

    // dump scores (thread's s values: 2*sx + 128*p and +1) into aliased buffer
    #pragma unroll
    for (int k = 0; k < 4; k++)
        #pragma unroll
        for (int p = 0; p < 3; p++) {
            scores[ty*4+k][2*sx   + 128*p] = acc[k][2*p];
            scores[ty*4+k][2*sx+1 + 128*p] = acc[k][2*p+1];
        }
    __syncthreads();

    // softmax: 4 warps, 2 rows each; write attn to global, keep normalized in smem
    int w = tid >> 5, lane = tid & 31;
    for (int r = w; r < 8; r += 4) {
        float vals[12];
        float m = -1e30f;
        #pragma unroll
        for (int i = 0; i < 12; i++) {
            vals[i] = scores[r][lane + 32*i];
            m = fmaxf(m, vals[i]);
        }
        #pragma unroll
        for (int off = 16; off; off >>= 1)
            m = fmaxf(m, __shfl_xor_sync(0xffffffffu, m, off));
        float sum = 0.f;
        #pragma unroll
        for (int i = 0; i < 12; i++) {
            float p;
            float xe = (vals[i] - m) * 1.4426950408889634f;
            asm("ex2.approx.f32 %0, %1;" : "=f"(p) : "f"(xe));
            vals[i] = p;
            sum += p;
        }
        #pragma unroll
        for (int off = 16; off; off >>= 1)
            sum += __shfl_xor_sync(0xffffffffu, sum, off);
        float inv = 1.0f / sum;
        size_t arow = ((size_t)bh*T + t0 + r) * S;
        #pragma unroll
        for (int i = 0; i < 12; i++) {
            float p = vals[i] * inv;
            scores[r][lane + 32*i] = p;
            attn[arow + lane + 32*i] = p;
        }
    }
    __syncthreads();

    // epilogue: out[t0+tl][d] = sum_s attn[tl][s] * value[s][d]
    int dx = sx; // 0..63, warp-coalesced value loads
    float acc2[4] = {0.f, 0.f, 0.f, 0.f};
    const float* vp = value + (size_t)bh*S*D + dx;
    #pragma unroll 2
    for (int s = 0; s < 384; s += 4) {
        float v0 = __ldg(vp + (size_t)(s+0)*D);
        float v1 = __ldg(vp + (size_t)(s+1)*D);
        float v2 = __ldg(vp + (size_t)(s+2)*D);
        float v3 = __ldg(vp + (size_t)(s+3)*D);
        #pragma unroll
        for (int k = 0; k < 4; k++) {
            float4 a = *(const float4*)&scores[ty*4+k][s];
            acc2[k] = fmaf(a.x, v0, fmaf(a.y, v1, fmaf(a.z, v2, fmaf(a.w, v3, acc2[k]))));
        }
    }
    #pragma unroll
    for (int k = 0; k < 4; k++)
        out[((size_t)bh*T + t0 + ty*4 + k)*D + dx] = acc2[k];
}

// ---------------------------------------------------------------------------
extern "C" void kernel_launch(void* const* d_in, const int* in_sizes, int n_in,
                              void* d_out, int out_size)
{
    (void)in_sizes; (void)n_in; (void)out_size;
    const float* query = (const float*)d_in[0];
    const float* key   = (const float*)d_in[1];
    const float* value = (const float*)d_in[2];
    const float* Wq    = (const float*)d_in[3];
    const float* Wk    = (const float*)d_in[4];
    const float* vw    = (const float*)d_in[5];
    float* out  = (float*)d_out;
    float* attn = out + OUT_ELEMS;

    proj_kernel<<<dim3(16, 6, 2), 256>>>(query, key, Wq, Wk);
    attn_kernel<<<dim3(48, 16), 128>>>(value, vw, out, attn);
}

// round 10
// speedup vs baseline: 1.2072x; 1.2072x over previous
#include <cuda_runtime.h>
#include <math.h>

#define BH 16
#define T 384
#define S 384
#define D 64
#define OUT_ELEMS (BH*T*D)   // 393216

typedef unsigned long long u64;

// Scratch: ta = tanh(qp), tb = tanh(kp), e-major f32: [bh][e][t] / [bh][e][s]
__device__ float4 g_taT4[BH*D*T/4];
__device__ float4 g_tbT4[BH*D*S/4];

// ---- packed f32x2 helpers (Blackwell sm_103a) ------------------------------
__device__ __forceinline__ u64 pk2(float lo, float hi) {
    u64 r; asm("mov.b64 %0, {%1,%2};" : "=l"(r) : "f"(lo), "f"(hi)); return r;
}
__device__ __forceinline__ void upk2(u64 v, float& lo, float& hi) {
    asm("mov.b64 {%0,%1}, %2;" : "=f"(lo), "=f"(hi) : "l"(v));
}
__device__ __forceinline__ u64 add2(u64 a, u64 b) {
    u64 r; asm("add.rn.f32x2 %0, %1, %2;" : "=l"(r) : "l"(a), "l"(b)); return r;
}
__device__ __forceinline__ u64 mul2(u64 a, u64 b) {
    u64 r; asm("mul.rn.f32x2 %0, %1, %2;" : "=l"(r) : "l"(a), "l"(b)); return r;
}
__device__ __forceinline__ u64 fma2(u64 a, u64 b, u64 c) {
    u64 r; asm("fma.rn.f32x2 %0, %1, %2, %3;" : "=l"(r) : "l"(a), "l"(b), "l"(c)); return r;
}
__device__ __forceinline__ float rcpf(float x) {
    float r; asm("rcp.approx.ftz.f32 %0, %1;" : "=f"(r) : "f"(x)); return r;
}

// ---------------------------------------------------------------------------
// Phase 1: taT[bh][e][t] = tanh( sum_d X[bh][t][d] * W[e][d] )
// grid (16 bh, 6 chunks of 64, 2 which), 256 threads
// ---------------------------------------------------------------------------
__global__ __launch_bounds__(256) void proj_kernel(
    const float* __restrict__ query, const float* __restrict__ key,
    const float* __restrict__ Wq, const float* __restrict__ Wk)
{
    __shared__ float Xs[64][65];
    __shared__ float Ws[64][65];
    int bh = blockIdx.x, chunk = blockIdx.y, which = blockIdx.z;
    const float* X = which ? key : query;
    const float* W = which ? Wk : Wq;
    float* outT = which ? (float*)g_tbT4 : (float*)g_taT4;
    int tid = threadIdx.x;

    for (int i = tid; i < 64*64; i += 256) {
        int r = i >> 6, c = i & 63;
        Xs[r][c] = X[((size_t)bh*T + (size_t)chunk*64 + r)*D + c];
        Ws[r][c] = W[i];
    }
    __syncthreads();

    int t  = tid & 63;
    int e0 = (tid >> 6) * 16;
    float acc[16];
    #pragma unroll
    for (int k = 0; k < 16; k++) acc[k] = 0.f;

    #pragma unroll 4
    for (int d = 0; d < 64; d++) {
        float xv = Xs[t][d];
        #pragma unroll
        for (int k = 0; k < 16; k++)
            acc[k] = fmaf(xv, Ws[e0+k][d], acc[k]);
    }
    #pragma unroll
    for (int k = 0; k < 16; k++)
        outT[((size_t)bh*D + e0 + k)*T + (size_t)chunk*64 + t] = tanhf(acc[k]);
}

// ---------------------------------------------------------------------------
// Phase 2: fused score + softmax + attn@value.
// tanh(qp+kp) = (ta+tb)/(1+ta*tb)  — tanh fully precomputed; hot loop is
// 3 packed f32x2 fma-pipe ops + 2 MUFU rcp per s-pair. MUFU floor 0.25cyc/elem.
// grid (48, 16), 256 threads. CTA: 8 t x 384 s; thread 2t x 3 s-pairs.
// ---------------------------------------------------------------------------
__global__ __launch_bounds__(256) void attn_kernel(
    const float* __restrict__ value, const float* __restrict__ v_w,
    float* __restrict__ out, float* __restrict__ attn)
{
    __shared__ __align__(16) float sh_tb[16*384];   // 24KB chunk; aliased as scores[8][384]
    __shared__ __align__(8)  u64 sh_ta2[64][8];     // (ta,ta) duplicated pairs
    __shared__ __align__(8)  u64 sh_vw2[64];        // (vw,vw)

    float (*scores)[384] = (float(*)[384])sh_tb;

    int bh  = blockIdx.y;
    int t0  = blockIdx.x * 8;
    int tid = threadIdx.x;

    // stage ta tile duplicated + vw duplicated
    const float* tabase = (const float*)g_taT4 + (size_t)bh*D*T;
    for (int i = tid; i < 64*8; i += 256) {
        int e = i >> 3, tl = i & 7;
        float a = tabase[(size_t)e*T + t0 + tl];
        sh_ta2[e][tl] = pk2(a, a);
    }
    if (tid < 64) { float v = v_w[tid]; sh_vw2[tid] = pk2(v, v); }

    int sx = tid & 63;   // s-pair lane (0..63)
    int tg = tid >> 6;   // t group (0..3), rows tg*2, tg*2+1

    float acc[2][6];
    #pragma unroll
    for (int k = 0; k < 2; k++)
        #pragma unroll
        for (int j = 0; j < 6; j++) acc[k][j] = 0.f;

    const u64 ONE2 = pk2(1.f, 1.f);
    const float4* tbbase4 = g_tbT4 + (size_t)bh*D*S/4;

    for (int c = 0; c < 4; c++) {
        __syncthreads();
        // load tb chunk: 16 e-rows x 384 s (24KB), coalesced float4, 6/thread
        const float4* src = tbbase4 + (size_t)c*16*S/4;
        float4* dst = (float4*)sh_tb;
        #pragma unroll
        for (int i = tid; i < 16*384/4; i += 256) dst[i] = src[i];
        __syncthreads();

        #pragma unroll
        for (int ec = 0; ec < 16; ec++) {
            int e = c*16 + ec;
            u64 vw2 = sh_vw2[e];
            u64 ta2[2], kk[3];
            #pragma unroll
            for (int k = 0; k < 2; k++) ta2[k] = sh_ta2[e][tg*2 + k];
            const u64* krow = (const u64*)&sh_tb[ec*384];
            #pragma unroll
            for (int p = 0; p < 3; p++) kk[p] = krow[sx + 64*p];

            #pragma unroll
            for (int k = 0; k < 2; k++)
                #pragma unroll
                for (int p = 0; p < 3; p++) {
                    u64 n2 = add2(ta2[k], kk[p]);
                    u64 d2 = fma2(ta2[k], kk[p], ONE2);
                    u64 num2 = mul2(vw2, n2);
                    float dl, dh, nl, nh;
                    upk2(d2, dl, dh);
                    upk2(num2, nl, nh);
                    acc[k][2*p]   = fmaf(nl, rcpf(dl), acc[k][2*p]);
                    acc[k][2*p+1] = fmaf(nh, rcpf(dh), acc[k][2*p+1]);
                }
        }
    }
    __syncthreads();

    // dump scores (thread's s values: 2*sx + 128*p and +1) into aliased buffer
    #pragma unroll
    for (int k = 0; k < 2; k++)
        #pragma unroll
        for (int p = 0; p < 3; p++) {
            scores[tg*2+k][2*sx   + 128*p] = acc[k][2*p];
            scores[tg*2+k][2*sx+1 + 128*p] = acc[k][2*p+1];
        }
    __syncthreads();

    // softmax: 8 warps, 1 row each; write attn to global, keep normalized in smem
    int w = tid >> 5, lane = tid & 31;
    {
        int r = w;
        float vals[12];
        float m = -1e30f;
        #pragma unroll
        for (int i = 0; i < 12; i++) {
            vals[i] = scores[r][lane + 32*i];
            m = fmaxf(m, vals[i]);
        }
        #pragma unroll
        for (int off = 16; off; off >>= 1)
            m = fmaxf(m, __shfl_xor_sync(0xffffffffu, m, off));
        float sum = 0.f;
        #pragma unroll
        for (int i = 0; i < 12; i++) {
            float p;
            float xe = (vals[i] - m) * 1.4426950408889634f;
            asm("ex2.approx.f32 %0, %1;" : "=f"(p) : "f"(xe));
            vals[i] = p;
            sum += p;
        }
        #pragma unroll
        for (int off = 16; off; off >>= 1)
            sum += __shfl_xor_sync(0xffffffffu, sum, off);
        float inv = 1.0f / sum;
        size_t arow = ((size_t)bh*T + t0 + r) * S;
        #pragma unroll
        for (int i = 0; i < 12; i++) {
            float p = vals[i] * inv;
            scores[r][lane + 32*i] = p;
            attn[arow + lane + 32*i] = p;
        }
    }
    __syncthreads();

    // epilogue: out[t0+tl][d] = sum_s attn[tl][s] * value[s][d]
    int dx = sx; // 0..63, warp-coalesced value loads
    float acc2[2] = {0.f, 0.f};
    const float* vp = value + (size_t)bh*S*D + dx;
    #pragma unroll 2
    for (int s = 0; s < 384; s += 4) {
        float v0 = __ldg(vp + (size_t)(s+0)*D);
        float v1 = __ldg(vp + (size_t)(s+1)*D);
        float v2 = __ldg(vp + (size_t)(s+2)*D);
        float v3 = __ldg(vp + (size_t)(s+3)*D);
        #pragma unroll
        for (int k = 0; k < 2; k++) {
            float4 a = *(const float4*)&scores[tg*2+k][s];
            acc2[k] = fmaf(a.x, v0, fmaf(a.y, v1, fmaf(a.z, v2, fmaf(a.w, v3, acc2[k]))));
        }
    }
    #pragma unroll
    for (int k = 0; k < 2; k++)
        out[((size_t)bh*T + t0 + tg*2 + k)*D + dx] = acc2[k];
}

// ---------------------------------------------------------------------------
extern "C" void kernel_launch(void* const* d_in, const int* in_sizes, int n_in,
                              void* d_out, int out_size)
{
    (void)in_sizes; (void)n_in; (void)out_size;
    const float* query = (const float*)d_in[0];
    const float* key   = (const float*)d_in[1];
    const float* value = (const float*)d_in[2];
    const float* Wq    = (const float*)d_in[3];
    const float* Wk    = (const float*)d_in[4];
    const float* vw    = (const float*)d_in[5];
    float* out  = (float*)d_out;
    float* attn = out + OUT_ELEMS;

    proj_kernel<<<dim3(16, 6, 2), 256>>>(query, key, Wq, Wk);
    attn_kernel<<<dim3(48, 16), 256>>>(value, vw, out, attn);
}

// round 11
// speedup vs baseline: 1.4038x; 1.1629x over previous
#include <cuda_runtime.h>
#include <math.h>

#define BH 16
#define T 384
#define S 384
#define D 64
#define OUT_ELEMS (BH*T*D)   // 393216

typedef unsigned long long u64;

// Scratch: Et = exp(2*qp), Es = exp(2*kp), e-major f32: [bh][e][t] / [bh][e][s]
__device__ float4 g_EtT4[BH*D*T/4];
__device__ float4 g_EsT4[BH*D*S/4];

// ---- packed f32x2 helpers (Blackwell sm_103a) ------------------------------
__device__ __forceinline__ u64 pk2(float lo, float hi) {
    u64 r; asm("mov.b64 %0, {%1,%2};" : "=l"(r) : "f"(lo), "f"(hi)); return r;
}
__device__ __forceinline__ void upk2(u64 v, float& lo, float& hi) {
    asm("mov.b64 {%0,%1}, %2;" : "=f"(lo), "=f"(hi) : "l"(v));
}
__device__ __forceinline__ u64 fma2(u64 a, u64 b, u64 c) {
    u64 r; asm("fma.rn.f32x2 %0, %1, %2, %3;" : "=l"(r) : "l"(a), "l"(b), "l"(c)); return r;
}
__device__ __forceinline__ float rcpf(float x) {
    float r; asm("rcp.approx.ftz.f32 %0, %1;" : "=f"(r) : "f"(x)); return r;
}

// ---------------------------------------------------------------------------
// Phase 1: EtT[bh][e][t] = exp( 2 * sum_d X[bh][t][d] * W[e][d] )
// grid (16 bh, 6 chunks of 64, 2 which), 256 threads
// ---------------------------------------------------------------------------
__global__ __launch_bounds__(256) void proj_kernel(
    const float* __restrict__ query, const float* __restrict__ key,
    const float* __restrict__ Wq, const float* __restrict__ Wk)
{
    __shared__ float Xs[64][65];
    __shared__ float Ws[64][65];
    int bh = blockIdx.x, chunk = blockIdx.y, which = blockIdx.z;
    const float* X = which ? key : query;
    const float* W = which ? Wk : Wq;
    float* outT = which ? (float*)g_EsT4 : (float*)g_EtT4;
    int tid = threadIdx.x;

    for (int i = tid; i < 64*64; i += 256) {
        int r = i >> 6, c = i & 63;
        Xs[r][c] = X[((size_t)bh*T + (size_t)chunk*64 + r)*D + c];
        Ws[r][c] = W[i];
    }
    __syncthreads();

    int t  = tid & 63;
    int e0 = (tid >> 6) * 16;
    float acc[16];
    #pragma unroll
    for (int k = 0; k < 16; k++) acc[k] = 0.f;

    #pragma unroll 4
    for (int d = 0; d < 64; d++) {
        float xv = Xs[t][d];
        #pragma unroll
        for (int k = 0; k < 16; k++)
            acc[k] = fmaf(xv, Ws[e0+k][d], acc[k]);
    }
    // exp(2x) = 2^(x * 2*log2(e)); fp32 exact path via exp2
    #pragma unroll
    for (int k = 0; k < 16; k++) {
        float p;
        float xe = acc[k] * 2.885390081777927f;  // 2*log2(e)
        asm("ex2.approx.ftz.f32 %0, %1;" : "=f"(p) : "f"(xe));
        outT[((size_t)bh*D + e0 + k)*T + (size_t)chunk*64 + t] = p;
    }
}

// ---------------------------------------------------------------------------
// Phase 2: fused score + softmax + attn@value.
// tanh(qp+kp) = 1 - 2/(Et*Es+1); the constant sum_e vw cancels in softmax,
// so score* = sum_e (-2 vw_e)/(Et*Es+1). Hot loop per s-pair:
//   1 packed fma2 (denoms) + 1 mul + 1 rcp + 2 mul + 1 packed fma2 (acc).
// grid (48, 16), 256 threads. CTA: 8 t x 384 s; thread 2t x 3 s-pairs.
// ---------------------------------------------------------------------------
__global__ __launch_bounds__(256) void attn_kernel(
    const float* __restrict__ value, const float* __restrict__ v_w,
    float* __restrict__ out, float* __restrict__ attn)
{
    __shared__ __align__(16) float sh_Es[16*384];   // 24KB chunk; aliased as scores[8][384]
    __shared__ __align__(8)  u64 sh_Et2[64][8];     // (Et,Et) duplicated pairs
    __shared__ __align__(8)  u64 sh_w2[64];         // (-2vw,-2vw)

    float (*scores)[384] = (float(*)[384])sh_Es;

    int bh  = blockIdx.y;
    int t0  = blockIdx.x * 8;
    int tid = threadIdx.x;

    // stage Et tile duplicated + w duplicated
    const float* Etbase = (const float*)g_EtT4 + (size_t)bh*D*T;
    for (int i = tid; i < 64*8; i += 256) {
        int e = i >> 3, tl = i & 7;
        float a = Etbase[(size_t)e*T + t0 + tl];
        sh_Et2[e][tl] = pk2(a, a);
    }
    if (tid < 64) { float v = -2.f * v_w[tid]; sh_w2[tid] = pk2(v, v); }

    int sx = tid & 63;   // s-pair lane (0..63)
    int tg = tid >> 6;   // t group (0..3), rows tg*2, tg*2+1

    u64 acc2[2][3];
    #pragma unroll
    for (int k = 0; k < 2; k++)
        #pragma unroll
        for (int p = 0; p < 3; p++) acc2[k][p] = pk2(0.f, 0.f);

    const u64 ONE2 = pk2(1.f, 1.f);
    const float4* Esbase4 = g_EsT4 + (size_t)bh*D*S/4;

    for (int c = 0; c < 4; c++) {
        __syncthreads();
        // load Es chunk: 16 e-rows x 384 s (24KB), coalesced float4, 6/thread
        const float4* src = Esbase4 + (size_t)c*16*S/4;
        float4* dst = (float4*)sh_Es;
        #pragma unroll
        for (int i = tid; i < 16*384/4; i += 256) dst[i] = src[i];
        __syncthreads();

        #pragma unroll
        for (int ec = 0; ec < 16; ec++) {
            int e = c*16 + ec;
            u64 w2 = sh_w2[e];
            u64 Et2[2], kk[3];
            #pragma unroll
            for (int k = 0; k < 2; k++) Et2[k] = sh_Et2[e][tg*2 + k];
            const u64* krow = (const u64*)&sh_Es[ec*384];
            #pragma unroll
            for (int p = 0; p < 3; p++) kk[p] = krow[sx + 64*p];

            #pragma unroll
            for (int k = 0; k < 2; k++)
                #pragma unroll
                for (int p = 0; p < 3; p++) {
                    u64 d2 = fma2(Et2[k], kk[p], ONE2);     // (Et*Es+1) x2
                    float dl, dh;
                    upk2(d2, dl, dh);
                    float inv = rcpf(dl * dh);              // one rcp per pair
                    float rl = inv * dh;                    // = 1/dl
                    float rh = inv * dl;                    // = 1/dh
                    acc2[k][p] = fma2(w2, pk2(rl, rh), acc2[k][p]);
                }
        }
    }
    __syncthreads();

    // dump scores (thread's s values: 2*sx + 128*p and +1) into aliased buffer
    #pragma unroll
    for (int k = 0; k < 2; k++)
        #pragma unroll
        for (int p = 0; p < 3; p++) {
            float lo, hi;
            upk2(acc2[k][p], lo, hi);
            scores[tg*2+k][2*sx   + 128*p] = lo;
            scores[tg*2+k][2*sx+1 + 128*p] = hi;
        }
    __syncthreads();

    // softmax: 8 warps, 1 row each; write attn to global, keep normalized in smem
    int w = tid >> 5, lane = tid & 31;
    {
        int r = w;
        float vals[12];
        float m = -1e30f;
        #pragma unroll
        for (int i = 0; i < 12; i++) {
            vals[i] = scores[r][lane + 32*i];
            m = fmaxf(m, vals[i]);
        }
        #pragma unroll
        for (int off = 16; off; off >>= 1)
            m = fmaxf(m, __shfl_xor_sync(0xffffffffu, m, off));
        float sum = 0.f;
        #pragma unroll
        for (int i = 0; i < 12; i++) {
            float p;
            float xe = (vals[i] - m) * 1.4426950408889634f;
            asm("ex2.approx.f32 %0, %1;" : "=f"(p) : "f"(xe));
            vals[i] = p;
            sum += p;
        }
        #pragma unroll
        for (int off = 16; off; off >>= 1)
            sum += __shfl_xor_sync(0xffffffffu, sum, off);
        float inv = 1.0f / sum;
        size_t arow = ((size_t)bh*T + t0 + r) * S;
        #pragma unroll
        for (int i = 0; i < 12; i++) {
            float p = vals[i] * inv;
            scores[r][lane + 32*i] = p;
            attn[arow + lane + 32*i] = p;
        }
    }
    __syncthreads();

    // epilogue: out[t0+tl][d] = sum_s attn[tl][s] * value[s][d]
    int dx = sx; // 0..63, warp-coalesced value loads
    float accv[2] = {0.f, 0.f};
    const float* vp = value + (size_t)bh*S*D + dx;
    #pragma unroll 2
    for (int s = 0; s < 384; s += 4) {
        float v0 = __ldg(vp + (size_t)(s+0)*D);
        float v1 = __ldg(vp + (size_t)(s+1)*D);
        float v2 = __ldg(vp + (size_t)(s+2)*D);
        float v3 = __ldg(vp + (size_t)(s+3)*D);
        #pragma unroll
        for (int k = 0; k < 2; k++) {
            float4 a = *(const float4*)&scores[tg*2+k][s];
            accv[k] = fmaf(a.x, v0, fmaf(a.y, v1, fmaf(a.z, v2, fmaf(a.w, v3, accv[k]))));
        }
    }
    #pragma unroll
    for (int k = 0; k < 2; k++)
        out[((size_t)bh*T + t0 + tg*2 + k)*D + dx] = accv[k];
}

// ---------------------------------------------------------------------------
extern "C" void kernel_launch(void* const* d_in, const int* in_sizes, int n_in,
                              void* d_out, int out_size)
{
    (void)in_sizes; (void)n_in; (void)out_size;
    const float* query = (const float*)d_in[0];
    const float* key   = (const float*)d_in[1];
    const float* value = (const float*)d_in[2];
    const float* Wq    = (const float*)d_in[3];
    const float* Wk    = (const float*)d_in[4];
    const float* vw    = (const float*)d_in[5];
    float* out  = (float*)d_out;
    float* attn = out + OUT_ELEMS;

    proj_kernel<<<dim3(16, 6, 2), 256>>>(query, key, Wq, Wk);
    attn_kernel<<<dim3(48, 16), 256>>>(value, vw, out, attn);
}

// round 12
// speedup vs baseline: 1.5470x; 1.1020x over previous
#include <cuda_runtime.h>
#include <math.h>

#define BH 16
#define T 384
#define S 384
#define D 64
#define OUT_ELEMS (BH*T*D)   // 393216

// Scratch: Et = exp(2*qp), Es = exp(2*kp), e-major f32: [bh][e][t] / [bh][e][s]
__device__ float4 g_EtT4[BH*D*T/4];
__device__ float4 g_EsT4[BH*D*S/4];

__device__ __forceinline__ float rcpf(float x) {
    float r; asm("rcp.approx.ftz.f32 %0, %1;" : "=f"(r) : "f"(x)); return r;
}

// ---------------------------------------------------------------------------
// Phase 1: EtT[bh][e][t] = exp( 2 * sum_d X[bh][t][d] * W[e][d] )
// grid (16 bh, 6 chunks of 64, 2 which), 256 threads
// ---------------------------------------------------------------------------
__global__ __launch_bounds__(256) void proj_kernel(
    const float* __restrict__ query, const float* __restrict__ key,
    const float* __restrict__ Wq, const float* __restrict__ Wk)
{
    __shared__ float Xs[64][65];
    __shared__ float Ws[64][65];
    int bh = blockIdx.x, chunk = blockIdx.y, which = blockIdx.z;
    const float* X = which ? key : query;
    const float* W = which ? Wk : Wq;
    float* outT = which ? (float*)g_EsT4 : (float*)g_EtT4;
    int tid = threadIdx.x;

    for (int i = tid; i < 64*64; i += 256) {
        int r = i >> 6, c = i & 63;
        Xs[r][c] = X[((size_t)bh*T + (size_t)chunk*64 + r)*D + c];
        Ws[r][c] = W[i];
    }
    __syncthreads();

    int t  = tid & 63;
    int e0 = (tid >> 6) * 16;
    float acc[16];
    #pragma unroll
    for (int k = 0; k < 16; k++) acc[k] = 0.f;

    #pragma unroll 4
    for (int d = 0; d < 64; d++) {
        float xv = Xs[t][d];
        #pragma unroll
        for (int k = 0; k < 16; k++)
            acc[k] = fmaf(xv, Ws[e0+k][d], acc[k]);
    }
    #pragma unroll
    for (int k = 0; k < 16; k++) {
        float p;
        float xe = acc[k] * 2.885390081777927f;  // 2*log2(e)
        asm("ex2.approx.ftz.f32 %0, %1;" : "=f"(p) : "f"(xe));
        outT[((size_t)bh*D + e0 + k)*T + (size_t)chunk*64 + t] = p;
    }
}

// ---------------------------------------------------------------------------
// Phase 2: fused score + softmax + attn@value.
// tanh(qp+kp) = 1 - 2/(Et*Es+1); constant sum_e vw cancels in softmax, so
// score* = sum_e (-2 vw_e)/(Et*Es+1). Pure scalar hot loop (breadth-first
// schedulable): per s-pair 2 FFMA(d) + FMUL(prod) + RCP + FMUL(w*inv) + 2 FFMA.
// grid (48, 16), 128 threads. CTA: 8 t x 384 s; thread tile 4t x 6s
// (12 independent rcp chains per e-step). Single wave: <=8 CTAs/SM @26KB.
// ---------------------------------------------------------------------------
__global__ __launch_bounds__(128) void attn_kernel(
    const float* __restrict__ value, const float* __restrict__ v_w,
    float* __restrict__ out, float* __restrict__ attn)
{
    __shared__ __align__(16) float sh_Es[16*384];  // 24KB chunk; aliased as scores[8][384]
    __shared__ float sh_Et[64][8];                 // [e][t-row]
    __shared__ float sh_w[64];                     // -2*vw

    float (*scores)[384] = (float(*)[384])sh_Es;

    int bh  = blockIdx.y;
    int t0  = blockIdx.x * 8;
    int tid = threadIdx.x;

    // stage Et tile [64 e][8 t] + weights
    const float* Etbase = (const float*)g_EtT4 + (size_t)bh*D*T;
    for (int i = tid; i < 64*8; i += 128) {
        int e = i >> 3, tl = i & 7;
        sh_Et[e][tl] = Etbase[(size_t)e*T + t0 + tl];
    }
    if (tid < 64) sh_w[tid] = -2.f * v_w[tid];

    int sx = tid & 63;   // s-pair lane (0..63); pairs sx+64p, p=0..2
    int tg = tid >> 6;   // t half (0..1): rows tg*4 .. tg*4+3

    float acc[4][6];
    #pragma unroll
    for (int k = 0; k < 4; k++)
        #pragma unroll
        for (int j = 0; j < 6; j++) acc[k][j] = 0.f;

    const float4* Esbase4 = g_EsT4 + (size_t)bh*D*S/4;

    for (int c = 0; c < 4; c++) {
        __syncthreads();
        // load Es chunk: 16 e-rows x 384 s (24KB), coalesced float4, 12/thread
        const float4* src = Esbase4 + (size_t)c*16*S/4;
        float4* dst = (float4*)sh_Es;
        #pragma unroll
        for (int i = tid; i < 16*384/4; i += 128) dst[i] = src[i];
        __syncthreads();

        #pragma unroll
        for (int ec = 0; ec < 16; ec++) {
            int e = c*16 + ec;
            float w = sh_w[e];
            float et[4];
            float2 kb[3];
            #pragma unroll
            for (int k = 0; k < 4; k++) et[k] = sh_Et[e][tg*4 + k];
            #pragma unroll
            for (int p = 0; p < 3; p++)
                kb[p] = *(const float2*)&sh_Es[ec*384 + 2*(sx + 64*p)];

            #pragma unroll
            for (int k = 0; k < 4; k++)
                #pragma unroll
                for (int p = 0; p < 3; p++) {
                    float dl = fmaf(et[k], kb[p].x, 1.f);
                    float dh = fmaf(et[k], kb[p].y, 1.f);
                    float inv = rcpf(dl * dh);
                    float wi = w * inv;
                    acc[k][2*p]   = fmaf(wi, dh, acc[k][2*p]);   // w/dl
                    acc[k][2*p+1] = fmaf(wi, dl, acc[k][2*p+1]); // w/dh
                }
        }
    }
    __syncthreads();

    // dump scores into the (now free) Es buffer, float2 stores
    #pragma unroll
    for (int k = 0; k < 4; k++)
        #pragma unroll
        for (int p = 0; p < 3; p++)
            *(float2*)&scores[tg*4+k][2*(sx + 64*p)] =
                make_float2(acc[k][2*p], acc[k][2*p+1]);
    __syncthreads();

    // softmax: 4 warps, 2 rows each; write attn to global, keep normalized in smem
    int w = tid >> 5, lane = tid & 31;
    for (int r = w; r < 8; r += 4) {
        float vals[12];
        float m = -1e30f;
        #pragma unroll
        for (int i = 0; i < 12; i++) {
            vals[i] = scores[r][lane + 32*i];
            m = fmaxf(m, vals[i]);
        }
        #pragma unroll
        for (int off = 16; off; off >>= 1)
            m = fmaxf(m, __shfl_xor_sync(0xffffffffu, m, off));
        float sum = 0.f;
        #pragma unroll
        for (int i = 0; i < 12; i++) {
            float p;
            float xe = (vals[i] - m) * 1.4426950408889634f;
            asm("ex2.approx.f32 %0, %1;" : "=f"(p) : "f"(xe));
            vals[i] = p;
            sum += p;
        }
        #pragma unroll
        for (int off = 16; off; off >>= 1)
            sum += __shfl_xor_sync(0xffffffffu, sum, off);
        float inv = 1.0f / sum;
        size_t arow = ((size_t)bh*T + t0 + r) * S;
        #pragma unroll
        for (int i = 0; i < 12; i++) {
            float p = vals[i] * inv;
            scores[r][lane + 32*i] = p;
            attn[arow + lane + 32*i] = p;
        }
    }
    __syncthreads();

    // epilogue: out[t0+tl][d] = sum_s attn[tl][s] * value[s][d]
    int dx = sx;             // 0..63, warp-coalesced value loads
    float accv[4] = {0.f, 0.f, 0.f, 0.f};   // rows tg*4 .. tg*4+3
    const float* vp = value + (size_t)bh*S*D + dx;
    #pragma unroll 2
    for (int s = 0; s < 384; s += 4) {
        float v0 = __ldg(vp + (size_t)(s+0)*D);
        float v1 = __ldg(vp + (size_t)(s+1)*D);
        float v2 = __ldg(vp + (size_t)(s+2)*D);
        float v3 = __ldg(vp + (size_t)(s+3)*D);
        #pragma unroll
        for (int k = 0; k < 4; k++) {
            float4 a = *(const float4*)&scores[tg*4+k][s];
            accv[k] = fmaf(a.x, v0, fmaf(a.y, v1, fmaf(a.z, v2, fmaf(a.w, v3, accv[k]))));
        }
    }
    #pragma unroll
    for (int k = 0; k < 4; k++)
        out[((size_t)bh*T + t0 + tg*4 + k)*D + dx] = accv[k];
}

// ---------------------------------------------------------------------------
extern "C" void kernel_launch(void* const* d_in, const int* in_sizes, int n_in,
                              void* d_out, int out_size)
{
    (void)in_sizes; (void)n_in; (void)out_size;
    const float* query = (const float*)d_in[0];
    const float* key   = (const float*)d_in[1];
    const float* value = (const float*)d_in[2];
    const float* Wq    = (const float*)d_in[3];
    const float* Wk    = (const float*)d_in[4];
    const float* vw    = (const float*)d_in[5];
    float* out  = (float*)d_out;
    float* attn = out + OUT_ELEMS;

    proj_kernel<<<dim3(16, 6, 2), 256>>>(query, key, Wq, Wk);
    attn_kernel<<<dim3(48, 16), 128>>>(value, vw, out, attn);
}